// round 15
// baseline (speedup 1.0000x reference)
#include <cuda_runtime.h>
#include <cuda_bf16.h>
#include <math.h>

#define NN 100000
#define EE 1000000
#define RR 500
#define DD 64
#define NB_N 98            // ceil(100000/1024)
#define NSH 16             // relation-counter shards
#define RPAD8 8            // 32B stride for sharded rel counters (8000 buckets)

typedef unsigned long long ull;

#define FMA2(d, a, b, c) \
    asm("fma.rn.f32x2 %0, %1, %2, %3;" : "=l"(d) : "l"(a), "l"(b), "l"(c))

__device__ __forceinline__ ull pack2(float lo, float hi) {
    return ((ull)__float_as_uint(hi) << 32) | (ull)__float_as_uint(lo);
}
__device__ __forceinline__ float lo2(ull u) { return __uint_as_float((unsigned)u); }
__device__ __forceinline__ float hi2(ull u) { return __uint_as_float((unsigned)(u >> 32)); }

// ---------------- scratch (device globals; all self-cleaning) -----------------
__device__ __align__(16) float g_P1[NN * DD];
__device__ __align__(16) float g_P2[NN * DD];
__device__ float g_q1[NN];
__device__ float g_q2[NN];
__device__ __align__(16) float g_P3p[RR * DD];
__device__ float g_q3[RR];
__device__ float g_R2[RR * DD];
__device__ ull   g_M12[DD * DD];     // packed (M1, M2)
__device__ float g_M3[DD * DD];
__device__ float g_c0[DD];
__device__ ull   g_va[DD];           // packed (M1^T a, M2^T a)
__device__ int   g_src_cnt[NN];                 // zeroed by k_scan_all after read
__device__ int   g_rel_cnt8[RR * NSH * RPAD8];  // sharded; zeroed by k_scan_all
__device__ int   g_src_off[NN + 1];
__device__ int   g_rel_off8[RR * NSH + 1];      // bucket offsets (r-major, shard-minor)
__device__ int   g_src_cur[NN];
__device__ int   g_rel_cur8[RR * NSH * RPAD8];
__device__ __align__(8) int2 g_src_pay[EE];   // (dst, rel) in src-CSR order
__device__ __align__(8) int2 g_rel_pay[EE];   // (src, dst) in rel-CSR order
__device__ ull   g_look[NB_N];           // decoupled-lookback (flag<<32 | agg)

// ---------------- helpers ----------------------------------------------------
__device__ __forceinline__ int blockExScan(int v, int* warpSums) {
    int lane = threadIdx.x & 31;
    int wid  = threadIdx.x >> 5;
    int nw   = blockDim.x >> 5;
    int inc = v;
#pragma unroll
    for (int o = 1; o < 32; o <<= 1) {
        int t = __shfl_up_sync(0xffffffffu, inc, o);
        if (lane >= o) inc += t;
    }
    if (lane == 31) warpSums[wid] = inc;
    __syncthreads();
    if (wid == 0) {
        int w = (lane < nw) ? warpSums[lane] : 0;
#pragma unroll
        for (int o = 1; o < 32; o <<= 1) {
            int t = __shfl_up_sync(0xffffffffu, w, o);
            if (lane >= o) w += t;
        }
        if (lane < nw) warpSums[lane] = w;
    }
    __syncthreads();
    int base = (wid > 0) ? warpSums[wid - 1] : 0;
    return base + inc - v;   // exclusive
}

__device__ __forceinline__ float leaky_exp(float lg) {
    lg = (lg >= 0.f) ? lg : 0.01f * lg;
    return expf(lg);
}

// ---------------- 1. composed weight matrices (16 CTAs, float4-staged) -------
// Also (block 0): va = pack2(M1^T a, M2^T a) via t = W_fc^T a, va = W_ent^T t.
__global__ void __launch_bounds__(256) k_precompute(const float* __restrict__ W_ent,
                                                    const float* __restrict__ W_relL,
                                                    const float* __restrict__ W_fc,
                                                    const float* __restrict__ b_ent,
                                                    const float* __restrict__ b_relL,
                                                    const float* __restrict__ b_fc,
                                                    const float* __restrict__ W_a) {
    __shared__ float sEnt[DD * DD];
    __shared__ float sRel[DD * DD];
    __shared__ float sFc[4 * 192];
    __shared__ float sT[128];
    int tid = threadIdx.x;
    int i0 = blockIdx.x * 4;
    {
        const float4* e4 = (const float4*)W_ent;
        const float4* r4 = (const float4*)W_relL;
        float4* sE4 = (float4*)sEnt;
        float4* sR4 = (float4*)sRel;
#pragma unroll
        for (int idx = tid; idx < DD * DD / 4; idx += 256) {
            sE4[idx] = e4[idx];
            sR4[idx] = r4[idx];
        }
        const float4* f4 = (const float4*)(W_fc + i0 * 192);
        float4* sF4 = (float4*)sFc;
        if (tid < 192) sF4[tid] = f4[tid];
    }
    __syncthreads();

    int i = i0 + (tid >> 6);
    int j = tid & 63;
    int fr = (tid >> 6) * 192;
    float a1 = 0.f, a2 = 0.f, a3 = 0.f;
#pragma unroll 8
    for (int k = 0; k < DD; k++) {
        float e = sEnt[k * DD + j];
        a1 = fmaf(sFc[fr + k], e, a1);
        a2 = fmaf(sFc[fr + 64 + k], e, a2);
        a3 = fmaf(sFc[fr + 128 + k], sRel[k * DD + j], a3);
    }
    g_M12[i * DD + j] = pack2(a1, a2);
    g_M3[i * DD + j] = a3;

    if (blockIdx.x == 0) {
        if (tid < DD) {
            float c = b_fc[tid];
#pragma unroll 8
            for (int k = 0; k < DD; k++) {
                c = fmaf(W_fc[tid * 192 + k], b_ent[k], c);
                c = fmaf(W_fc[tid * 192 + 64 + k], b_ent[k], c);
                c = fmaf(W_fc[tid * 192 + 128 + k], b_relL[k], c);
            }
            g_c0[tid] = c;
        }
        // t1[k] = sum_i W_fcA[i][k] a[i]; t2[k] = sum_i W_fcB[i][k] a[i]
        if (tid < 128) {
            int k = tid & 63;
            int off = (tid < 64) ? 0 : 64;
            float acc = 0.f;
#pragma unroll 8
            for (int ii = 0; ii < 64; ii++)
                acc = fmaf(W_fc[ii * 192 + off + k], W_a[ii], acc);
            sT[tid] = acc;
        }
        __syncthreads();
        // va[j] = sum_k W_ent[k][j] * t[k]
        if (tid < DD) {
            float v1 = 0.f, v2 = 0.f;
#pragma unroll 8
            for (int k = 0; k < DD; k++) {
                float e = sEnt[k * DD + tid];
                v1 = fmaf(e, sT[k], v1);
                v2 = fmaf(e, sT[64 + k], v2);
            }
            g_va[tid] = pack2(v1, v2);
        }
    }
}

// ---------------- 2. relation tables: P3p, q3, R2 ----------------------------
__global__ void k_rel_proj(const float* __restrict__ rel_embed,
                           const float* __restrict__ W_relL,
                           const float* __restrict__ b_relL,
                           const float* __restrict__ W_rel2,
                           const float* __restrict__ b_rel2,
                           const float* __restrict__ W_a,
                           const float* __restrict__ b_a) {
    int r = blockIdx.x * 4 + (threadIdx.x >> 5);
    int lane = threadIdx.x & 31;
    if (r >= RR) return;
    float x0 = rel_embed[r * DD + lane];
    float x1 = rel_embed[r * DD + 32 + lane];
    int i0 = lane, i1 = lane + 32;
    float rl0 = b_relL[i0], rl1 = b_relL[i1];
    float p0 = g_c0[i0], p1 = g_c0[i1];
#pragma unroll
    for (int k = 0; k < DD; k++) {
        float xk = (k < 32) ? __shfl_sync(0xffffffffu, x0, k)
                            : __shfl_sync(0xffffffffu, x1, k - 32);
        rl0 = fmaf(xk, W_relL[i0 * DD + k], rl0);
        rl1 = fmaf(xk, W_relL[i1 * DD + k], rl1);
        p0  = fmaf(xk, g_M3[i0 * DD + k], p0);
        p1  = fmaf(xk, g_M3[i1 * DD + k], p1);
    }
    g_P3p[r * DD + i0] = p0;
    g_P3p[r * DD + i1] = p1;
    float r20 = b_rel2[i0], r21 = b_rel2[i1];
#pragma unroll
    for (int k = 0; k < DD; k++) {
        float rk = (k < 32) ? __shfl_sync(0xffffffffu, rl0, k)
                            : __shfl_sync(0xffffffffu, rl1, k - 32);
        r20 = fmaf(rk, W_rel2[i0 * DD + k], r20);
        r21 = fmaf(rk, W_rel2[i1 * DD + k], r21);
    }
    g_R2[r * DD + i0] = r20;
    g_R2[r * DD + i1] = r21;
    float q = fmaf(p0, W_a[i0], p1 * W_a[i1]);
#pragma unroll
    for (int o = 16; o > 0; o >>= 1) q += __shfl_xor_sync(0xffffffffu, q, o);
    if (lane == 0) g_q3[r] = q + b_a[0];
}

// ---------------- 3. node tables (k-split x in regs; high occupancy) ---------
// blockIdx.y selects output half [y*32, y*32+32). y==0 also computes q1/q2.
// x is loaded per k-half (32 regs), reloaded per output group (L1-resident).
__global__ void __launch_bounds__(128, 6) k_node_proj(const float* __restrict__ ent) {
    __shared__ ull sM[32 * DD];   // 16KB: this half's weight rows
    __shared__ ull sVa[DD];
    int tid = threadIdx.x;
    int yb = blockIdx.y;
    for (int idx = tid; idx < 32 * DD; idx += 128)
        sM[idx] = g_M12[yb * 32 * DD + idx];
    if (yb == 0)
        for (int idx = tid; idx < DD; idx += 128) sVa[idx] = g_va[idx];
    __syncthreads();

    int node = blockIdx.x * 128 + tid;
    if (node >= NN) return;
    const float4* xr = (const float4*)(ent + node * DD);

    if (yb == 0) {
        ull qa = 0ULL, qb = 0ULL;
#pragma unroll
        for (int kh = 0; kh < 2; kh++) {
            float xs[32];
#pragma unroll
            for (int u = 0; u < 8; u++) {
                float4 v = xr[kh * 8 + u];
                xs[4 * u + 0] = v.x; xs[4 * u + 1] = v.y;
                xs[4 * u + 2] = v.z; xs[4 * u + 3] = v.w;
            }
#pragma unroll 8
            for (int k = 0; k < 32; k += 2) {
                FMA2(qa, pack2(xs[k], xs[k]), sVa[kh * 32 + k], qa);
                FMA2(qb, pack2(xs[k + 1], xs[k + 1]), sVa[kh * 32 + k + 1], qb);
            }
        }
        g_q1[node] = lo2(qa) + lo2(qb);
        g_q2[node] = hi2(qa) + hi2(qb);
    }
#pragma unroll 1
    for (int g = 0; g < 2; g++) {
        ull acc[16];
#pragma unroll
        for (int ii = 0; ii < 16; ii++) acc[ii] = 0ULL;
#pragma unroll 1
        for (int kh = 0; kh < 2; kh++) {
            float xs[32];
#pragma unroll
            for (int u = 0; u < 8; u++) {
                float4 v = xr[kh * 8 + u];
                xs[4 * u + 0] = v.x; xs[4 * u + 1] = v.y;
                xs[4 * u + 2] = v.z; xs[4 * u + 3] = v.w;
            }
#pragma unroll 4
            for (int k = 0; k < 32; k++) {
                ull xx = pack2(xs[k], xs[k]);
                int kk = kh * 32 + k;
#pragma unroll
                for (int ii = 0; ii < 16; ii++) {
                    FMA2(acc[ii], xx, sM[(g * 16 + ii) * DD + kk], acc[ii]);
                }
            }
        }
#pragma unroll
        for (int ii = 0; ii < 16; ii += 4) {
            int i = yb * 32 + g * 16 + ii;
            float p10 = lo2(acc[ii]),     p20 = hi2(acc[ii]);
            float p11 = lo2(acc[ii + 1]), p21 = hi2(acc[ii + 1]);
            float p12 = lo2(acc[ii + 2]), p22 = hi2(acc[ii + 2]);
            float p13 = lo2(acc[ii + 3]), p23 = hi2(acc[ii + 3]);
            *(float4*)&g_P1[node * DD + i] = make_float4(p10, p11, p12, p13);
            *(float4*)&g_P2[node * DD + i] = make_float4(p20, p21, p22, p23);
        }
    }
}

// ---------------- 4. counts (sharded rel counters; resets lookback) ----------
__global__ void __launch_bounds__(256) k_count(const int4* __restrict__ src4,
                                               const int4* __restrict__ rel4) {
    if (blockIdx.x == 0) {
        for (int k = threadIdx.x; k < NB_N; k += 256) g_look[k] = 0ULL;
    }
    int t = blockIdx.x * blockDim.x + threadIdx.x;
    if (t >= EE / 4) return;
    int sh = threadIdx.x & (NSH - 1);
    int4 s = src4[t], r = rel4[t];
    atomicAdd(&g_src_cnt[s.x], 1);
    atomicAdd(&g_src_cnt[s.y], 1);
    atomicAdd(&g_src_cnt[s.z], 1);
    atomicAdd(&g_src_cnt[s.w], 1);
    atomicAdd(&g_rel_cnt8[(r.x * NSH + sh) * RPAD8], 1);
    atomicAdd(&g_rel_cnt8[(r.y * NSH + sh) * RPAD8], 1);
    atomicAdd(&g_rel_cnt8[(r.z * NSH + sh) * RPAD8], 1);
    atomicAdd(&g_rel_cnt8[(r.w * NSH + sh) * RPAD8], 1);
}

// ---------------- 5. fused scan (decoupled lookback; co-residency-safe) ------
__global__ void __launch_bounds__(1024) k_scan_all() {
    __shared__ int ws[32];
    __shared__ int sPrefix;
    __shared__ int sCarry;
    int b = blockIdx.x;
    int tid = threadIdx.x;
    int i = b * 1024 + tid;
    int v = (i < NN) ? g_src_cnt[i] : 0;
    int ex = blockExScan(v, ws);
    if (tid == 1023) {
        ull word = (1ULL << 32) | (ull)(unsigned)(ex + v);
        atomicExch(&g_look[b], word);
    }
    if (b == 0) {
        __syncthreads();
        if (tid == 0) sCarry = 0;
        __syncthreads();
        for (int ch = 0; ch < (RR * NSH + 1023) / 1024; ch++) {
            int idx = ch * 1024 + tid;
            int vr = (idx < RR * NSH) ? g_rel_cnt8[idx * RPAD8] : 0;
            int exr = blockExScan(vr, ws) + sCarry;
            if (idx < RR * NSH) {
                g_rel_off8[idx] = exr;
                g_rel_cur8[idx * RPAD8] = exr;
                g_rel_cnt8[idx * RPAD8] = 0;          // self-clean
            }
            __syncthreads();
            if (tid == 1023) sCarry = exr + vr;
            __syncthreads();
        }
        if (tid == 0) g_rel_off8[RR * NSH] = EE;
    }
    if (tid < 32) {
        int acc = 0;
        for (int k = tid; k < b; k += 32) {
            ull w;
            do { w = atomicAdd(&g_look[k], 0ULL); } while ((w >> 32) == 0ULL);
            acc += (int)(unsigned)w;
        }
#pragma unroll
        for (int o = 16; o > 0; o >>= 1) acc += __shfl_down_sync(0xffffffffu, acc, o);
        if (tid == 0) sPrefix = acc;
    }
    __syncthreads();
    int pre = sPrefix;
    if (i < NN) {
        int off = ex + pre;
        g_src_off[i] = off;
        g_src_cur[i] = off;
        g_src_cnt[i] = 0;                      // self-clean
    }
    if (b == 0 && tid == 0) g_src_off[NN] = EE;
}

// ---------------- 6. fill both CSRs (sharded rel cursors) --------------------
__global__ void __launch_bounds__(256) k_fill(const int4* __restrict__ src4,
                                              const int4* __restrict__ dst4,
                                              const int4* __restrict__ rel4) {
    int t = blockIdx.x * blockDim.x + threadIdx.x;
    if (t >= EE / 4) return;
    int sh = threadIdx.x & (NSH - 1);
    int4 s = src4[t], d = dst4[t], r = rel4[t];
    g_src_pay[atomicAdd(&g_src_cur[s.x], 1)] = make_int2(d.x, r.x);
    g_src_pay[atomicAdd(&g_src_cur[s.y], 1)] = make_int2(d.y, r.y);
    g_src_pay[atomicAdd(&g_src_cur[s.z], 1)] = make_int2(d.z, r.z);
    g_src_pay[atomicAdd(&g_src_cur[s.w], 1)] = make_int2(d.w, r.w);
    g_rel_pay[atomicAdd(&g_rel_cur8[(r.x * NSH + sh) * RPAD8], 1)] = make_int2(s.x, d.x);
    g_rel_pay[atomicAdd(&g_rel_cur8[(r.y * NSH + sh) * RPAD8], 1)] = make_int2(s.y, d.y);
    g_rel_pay[atomicAdd(&g_rel_cur8[(r.z * NSH + sh) * RPAD8], 1)] = make_int2(s.z, d.z);
    g_rel_pay[atomicAdd(&g_rel_cur8[(r.w * NSH + sh) * RPAD8], 1)] = make_int2(s.w, d.w);
}

// ---------------- 7. node aggregation (R8-proven) ----------------------------
__global__ void __launch_bounds__(256) k_node_agg(float* __restrict__ out) {
    const float4* P1 = (const float4*)g_P1;
    const float4* P2 = (const float4*)g_P2;
    const float4* P3 = (const float4*)g_P3p;
    int wid = threadIdx.x >> 5;
    int lane = threadIdx.x & 31;
    int n = blockIdx.x * 8 + wid;
    if (n >= NN) return;
    int j0 = g_src_off[n];
    int j1 = g_src_off[n + 1];
    int half = lane >> 4;
    int q = lane & 15;
    float q1n = g_q1[n];
    float4 acc = make_float4(0.f, 0.f, 0.f, 0.f);
    float bsum = 0.f;
    int j = j0 + half;
    for (; j + 2 < j1; j += 4) {
        int2 pA = g_src_pay[j];
        int2 pB = g_src_pay[j + 2];
        float lA = q1n + g_q2[pA.x] + g_q3[pA.y];
        float lB = q1n + g_q2[pB.x] + g_q3[pB.y];
        float bA = leaky_exp(lA), bB = leaky_exp(lB);
        float4 vA = P2[pA.x * 16 + q];
        float4 tA = P3[pA.y * 16 + q];
        float4 vB = P2[pB.x * 16 + q];
        float4 tB = P3[pB.y * 16 + q];
        acc.x = fmaf(bA, vA.x + tA.x, acc.x); acc.x = fmaf(bB, vB.x + tB.x, acc.x);
        acc.y = fmaf(bA, vA.y + tA.y, acc.y); acc.y = fmaf(bB, vB.y + tB.y, acc.y);
        acc.z = fmaf(bA, vA.z + tA.z, acc.z); acc.z = fmaf(bB, vB.z + tB.z, acc.z);
        acc.w = fmaf(bA, vA.w + tA.w, acc.w); acc.w = fmaf(bB, vB.w + tB.w, acc.w);
        bsum += bA + bB;
    }
    if (j < j1) {
        int2 p = g_src_pay[j];
        float lg = q1n + g_q2[p.x] + g_q3[p.y];
        float b = leaky_exp(lg);
        float4 v = P2[p.x * 16 + q];
        float4 tq = P3[p.y * 16 + q];
        acc.x = fmaf(b, v.x + tq.x, acc.x);
        acc.y = fmaf(b, v.y + tq.y, acc.y);
        acc.z = fmaf(b, v.z + tq.z, acc.z);
        acc.w = fmaf(b, v.w + tq.w, acc.w);
        bsum += b;
    }
    acc.x += __shfl_down_sync(0xffffffffu, acc.x, 16);
    acc.y += __shfl_down_sync(0xffffffffu, acc.y, 16);
    acc.z += __shfl_down_sync(0xffffffffu, acc.z, 16);
    acc.w += __shfl_down_sync(0xffffffffu, acc.w, 16);
    bsum  += __shfl_down_sync(0xffffffffu, bsum, 16);
    if (half == 0) {
        float4 h;
        if (j1 > j0) {
            float inv = 1.f / bsum;
            float4 p1v = P1[n * 16 + q];
            h.x = p1v.x + acc.x * inv;
            h.y = p1v.y + acc.y * inv;
            h.z = p1v.z + acc.z * inv;
            h.w = p1v.w + acc.w * inv;
        } else {
            h = make_float4(0.f, 0.f, 0.f, 0.f);
        }
        ((float4*)out)[n * 16 + q] = h;
    }
}

// ---------------- 8. fused relation pooling + output (R8-proven) -------------
__global__ void __launch_bounds__(512) k_rel_pool_out(const float4* __restrict__ h4,
                                                      const float* __restrict__ W_rel3,
                                                      const float* __restrict__ b_rel3,
                                                      float* __restrict__ out) {
    __shared__ float4 sred[16][32];
    __shared__ float smean[192];
    int r = blockIdx.x;
    int b0 = g_rel_off8[r * NSH];
    int b1 = g_rel_off8[(r + 1) * NSH];
    int cnt = b1 - b0;
    int w = threadIdx.x >> 5;
    int lane = threadIdx.x & 31;
    int isDst = lane >> 4;
    int q = lane & 15;
    float4 acc = make_float4(0.f, 0.f, 0.f, 0.f);
    int j = b0 + w;
    for (; j + 48 < b1; j += 64) {
        int2 p0 = g_rel_pay[j];
        int2 p1 = g_rel_pay[j + 16];
        int2 p2 = g_rel_pay[j + 32];
        int2 p3 = g_rel_pay[j + 48];
        int n0 = isDst ? p0.y : p0.x;
        int n1 = isDst ? p1.y : p1.x;
        int n2 = isDst ? p2.y : p2.x;
        int n3 = isDst ? p3.y : p3.x;
        float4 v0 = h4[n0 * 16 + q];
        float4 v1 = h4[n1 * 16 + q];
        float4 v2 = h4[n2 * 16 + q];
        float4 v3 = h4[n3 * 16 + q];
        acc.x += (v0.x + v1.x) + (v2.x + v3.x);
        acc.y += (v0.y + v1.y) + (v2.y + v3.y);
        acc.z += (v0.z + v1.z) + (v2.z + v3.z);
        acc.w += (v0.w + v1.w) + (v2.w + v3.w);
    }
    for (; j < b1; j += 16) {
        int2 p = g_rel_pay[j];
        int n = isDst ? p.y : p.x;
        float4 v = h4[n * 16 + q];
        acc.x += v.x; acc.y += v.y; acc.z += v.z; acc.w += v.w;
    }
    sred[w][lane] = acc;
    __syncthreads();
    if (w == 0) {
        float4 s = sred[0][lane];
#pragma unroll
        for (int k = 1; k < 16; k++) {
            float4 t = sred[k][lane];
            s.x += t.x; s.y += t.y; s.z += t.z; s.w += t.w;
        }
        float inv = 1.f / (float)max(cnt, 1);
        int base = isDst * 64 + q * 4;
        smean[base + 0] = s.x * inv;
        smean[base + 1] = s.y * inv;
        smean[base + 2] = s.z * inv;
        smean[base + 3] = s.w * inv;
    } else if (w == 1) {
        float sc = (cnt > 0) ? 1.f : 0.f;
        smean[128 + lane] = g_R2[r * DD + lane] * sc;
        smean[160 + lane] = g_R2[r * DD + 32 + lane] * sc;
    }
    __syncthreads();
    if (threadIdx.x < DD) {
        int i = threadIdx.x;
        float h = b_rel3[i];
#pragma unroll 8
        for (int jj = 0; jj < 192; jj++)
            h = fmaf(W_rel3[i * 192 + jj], smean[jj], h);
        out[NN * DD + r * DD + i] = h;
    }
}

// ---------------- launcher ---------------------------------------------------
extern "C" void kernel_launch(void* const* d_in, const int* in_sizes, int n_in,
                              void* d_out, int out_size) {
    const float* ent_embed = (const float*)d_in[0];
    const float* rel_embed = (const float*)d_in[1];
    const float* W_ent  = (const float*)d_in[2];
    const float* b_ent  = (const float*)d_in[3];
    const float* W_relL = (const float*)d_in[4];
    const float* b_relL = (const float*)d_in[5];
    const float* W_rel2 = (const float*)d_in[6];
    const float* b_rel2 = (const float*)d_in[7];
    const float* W_rel3 = (const float*)d_in[8];
    const float* b_rel3 = (const float*)d_in[9];
    const float* W_a    = (const float*)d_in[10];
    const float* b_a    = (const float*)d_in[11];
    const float* W_fc   = (const float*)d_in[12];
    const float* b_fc   = (const float*)d_in[13];
    const int* src_idx = (const int*)d_in[14];
    const int* dst_idx = (const int*)d_in[15];
    const int* rel_idx = (const int*)d_in[16];
    float* out = (float*)d_out;

    static cudaStream_t s2 = nullptr;
    static cudaEvent_t evF = nullptr, evJ = nullptr;
    if (s2 == nullptr) {
        cudaStreamCreateWithFlags(&s2, cudaStreamNonBlocking);
        cudaEventCreateWithFlags(&evF, cudaEventDisableTiming);
        cudaEventCreateWithFlags(&evJ, cudaEventDisableTiming);
    }

    const int4* s4 = (const int4*)src_idx;
    const int4* d4 = (const int4*)dst_idx;
    const int4* r4 = (const int4*)rel_idx;

    // fork (execution deps via events; submission order keeps k_node_proj in
    // the profiler's capture slot)
    cudaEventRecord(evF, 0);
    cudaStreamWaitEvent(s2, evF, 0);

    k_precompute<<<16, 256>>>(W_ent, W_relL, W_fc, b_ent, b_relL, b_fc, W_a);     // 1
    k_rel_proj<<<(RR + 3) / 4, 128>>>(rel_embed, W_relL, b_relL,
                                      W_rel2, b_rel2, W_a, b_a);                   // 2
    k_count<<<(EE / 4 + 255) / 256, 256, 0, s2>>>(s4, r4);                         // 3
    {
        dim3 grid((NN + 127) / 128, 2);
        k_node_proj<<<grid, 128>>>(ent_embed);                                     // 4
    }
    k_scan_all<<<NB_N, 1024, 0, s2>>>();                                           // 5
    k_fill<<<(EE / 4 + 255) / 256, 256, 0, s2>>>(s4, d4, r4);                      // 6
    cudaEventRecord(evJ, s2);

    // join, then aggregation + fused relation output
    cudaStreamWaitEvent(0, evJ, 0);
    k_node_agg<<<(NN + 7) / 8, 256>>>(out);                                        // 7
    k_rel_pool_out<<<RR, 512>>>((const float4*)out, W_rel3, b_rel3, out);          // 8
}

// round 16
// speedup vs baseline: 1.0108x; 1.0108x over previous
#include <cuda_runtime.h>
#include <cuda_bf16.h>
#include <math.h>

#define NN 100000
#define EE 1000000
#define RR 500
#define DD 64
#define NB_N 98            // ceil(100000/1024)
#define NSH 16             // relation-counter shards
#define RPAD8 8            // 32B stride for sharded rel counters (8000 buckets)

typedef unsigned long long ull;

#define FMA2(d, a, b, c) \
    asm("fma.rn.f32x2 %0, %1, %2, %3;" : "=l"(d) : "l"(a), "l"(b), "l"(c))

__device__ __forceinline__ ull pack2(float lo, float hi) {
    return ((ull)__float_as_uint(hi) << 32) | (ull)__float_as_uint(lo);
}
__device__ __forceinline__ float lo2(ull u) { return __uint_as_float((unsigned)u); }
__device__ __forceinline__ float hi2(ull u) { return __uint_as_float((unsigned)(u >> 32)); }

// ---------------- scratch (device globals; all self-cleaning) -----------------
__device__ __align__(16) float g_P1[NN * DD];
__device__ __align__(16) float g_P2[NN * DD];
__device__ float g_q1[NN];
__device__ float g_q2[NN];
__device__ __align__(16) float g_P3p[RR * DD];
__device__ float g_q3[RR];
__device__ float g_R2[RR * DD];
__device__ ull   g_M12[DD * DD];     // packed (M1, M2)
__device__ float g_M3[DD * DD];
__device__ float g_c0[DD];
__device__ ull   g_va[DD];           // packed (M1^T a, M2^T a)
__device__ int   g_src_cnt[NN];                 // zeroed by k_scan_all after read
__device__ int   g_rel_cnt8[RR * NSH * RPAD8];  // sharded; zeroed by k_scan_all
__device__ int   g_src_off[NN + 1];
__device__ int   g_rel_off8[RR * NSH + 1];      // bucket offsets (r-major, shard-minor)
__device__ int   g_src_cur[NN];
__device__ int   g_rel_cur8[RR * NSH * RPAD8];
__device__ __align__(8) int2 g_src_pay[EE];   // (dst, rel) in src-CSR order
__device__ __align__(8) int2 g_rel_pay[EE];   // (src, dst) in rel-CSR order
__device__ ull   g_look[NB_N];           // decoupled-lookback (flag<<32 | agg)

// ---------------- helpers ----------------------------------------------------
__device__ __forceinline__ int blockExScan(int v, int* warpSums) {
    int lane = threadIdx.x & 31;
    int wid  = threadIdx.x >> 5;
    int nw   = blockDim.x >> 5;
    int inc = v;
#pragma unroll
    for (int o = 1; o < 32; o <<= 1) {
        int t = __shfl_up_sync(0xffffffffu, inc, o);
        if (lane >= o) inc += t;
    }
    if (lane == 31) warpSums[wid] = inc;
    __syncthreads();
    if (wid == 0) {
        int w = (lane < nw) ? warpSums[lane] : 0;
#pragma unroll
        for (int o = 1; o < 32; o <<= 1) {
            int t = __shfl_up_sync(0xffffffffu, w, o);
            if (lane >= o) w += t;
        }
        if (lane < nw) warpSums[lane] = w;
    }
    __syncthreads();
    int base = (wid > 0) ? warpSums[wid - 1] : 0;
    return base + inc - v;   // exclusive
}

__device__ __forceinline__ float leaky_exp(float lg) {
    lg = (lg >= 0.f) ? lg : 0.01f * lg;
    return expf(lg);
}

// ---------------- 1. composed weight matrices (16 CTAs, float4-staged) -------
__global__ void __launch_bounds__(256) k_precompute(const float* __restrict__ W_ent,
                                                    const float* __restrict__ W_relL,
                                                    const float* __restrict__ W_fc,
                                                    const float* __restrict__ b_ent,
                                                    const float* __restrict__ b_relL,
                                                    const float* __restrict__ b_fc,
                                                    const float* __restrict__ W_a) {
    __shared__ float sEnt[DD * DD];
    __shared__ float sRel[DD * DD];
    __shared__ float sFc[4 * 192];
    __shared__ float sT[128];
    int tid = threadIdx.x;
    int i0 = blockIdx.x * 4;
    {
        const float4* e4 = (const float4*)W_ent;
        const float4* r4 = (const float4*)W_relL;
        float4* sE4 = (float4*)sEnt;
        float4* sR4 = (float4*)sRel;
#pragma unroll
        for (int idx = tid; idx < DD * DD / 4; idx += 256) {
            sE4[idx] = e4[idx];
            sR4[idx] = r4[idx];
        }
        const float4* f4 = (const float4*)(W_fc + i0 * 192);
        float4* sF4 = (float4*)sFc;
        if (tid < 192) sF4[tid] = f4[tid];
    }
    __syncthreads();

    int i = i0 + (tid >> 6);
    int j = tid & 63;
    int fr = (tid >> 6) * 192;
    float a1 = 0.f, a2 = 0.f, a3 = 0.f;
#pragma unroll 8
    for (int k = 0; k < DD; k++) {
        float e = sEnt[k * DD + j];
        a1 = fmaf(sFc[fr + k], e, a1);
        a2 = fmaf(sFc[fr + 64 + k], e, a2);
        a3 = fmaf(sFc[fr + 128 + k], sRel[k * DD + j], a3);
    }
    g_M12[i * DD + j] = pack2(a1, a2);
    g_M3[i * DD + j] = a3;

    if (blockIdx.x == 0) {
        if (tid < DD) {
            float c = b_fc[tid];
#pragma unroll 8
            for (int k = 0; k < DD; k++) {
                c = fmaf(W_fc[tid * 192 + k], b_ent[k], c);
                c = fmaf(W_fc[tid * 192 + 64 + k], b_ent[k], c);
                c = fmaf(W_fc[tid * 192 + 128 + k], b_relL[k], c);
            }
            g_c0[tid] = c;
        }
        if (tid < 128) {
            int k = tid & 63;
            int off = (tid < 64) ? 0 : 64;
            float acc = 0.f;
#pragma unroll 8
            for (int ii = 0; ii < 64; ii++)
                acc = fmaf(W_fc[ii * 192 + off + k], W_a[ii], acc);
            sT[tid] = acc;
        }
        __syncthreads();
        if (tid < DD) {
            float v1 = 0.f, v2 = 0.f;
#pragma unroll 8
            for (int k = 0; k < DD; k++) {
                float e = sEnt[k * DD + tid];
                v1 = fmaf(e, sT[k], v1);
                v2 = fmaf(e, sT[64 + k], v2);
            }
            g_va[tid] = pack2(v1, v2);
        }
    }
}

// ---------------- 2. relation tables: P3p, q3, R2 ----------------------------
__global__ void k_rel_proj(const float* __restrict__ rel_embed,
                           const float* __restrict__ W_relL,
                           const float* __restrict__ b_relL,
                           const float* __restrict__ W_rel2,
                           const float* __restrict__ b_rel2,
                           const float* __restrict__ W_a,
                           const float* __restrict__ b_a) {
    int r = blockIdx.x * 4 + (threadIdx.x >> 5);
    int lane = threadIdx.x & 31;
    if (r >= RR) return;
    float x0 = rel_embed[r * DD + lane];
    float x1 = rel_embed[r * DD + 32 + lane];
    int i0 = lane, i1 = lane + 32;
    float rl0 = b_relL[i0], rl1 = b_relL[i1];
    float p0 = g_c0[i0], p1 = g_c0[i1];
#pragma unroll
    for (int k = 0; k < DD; k++) {
        float xk = (k < 32) ? __shfl_sync(0xffffffffu, x0, k)
                            : __shfl_sync(0xffffffffu, x1, k - 32);
        rl0 = fmaf(xk, W_relL[i0 * DD + k], rl0);
        rl1 = fmaf(xk, W_relL[i1 * DD + k], rl1);
        p0  = fmaf(xk, g_M3[i0 * DD + k], p0);
        p1  = fmaf(xk, g_M3[i1 * DD + k], p1);
    }
    g_P3p[r * DD + i0] = p0;
    g_P3p[r * DD + i1] = p1;
    float r20 = b_rel2[i0], r21 = b_rel2[i1];
#pragma unroll
    for (int k = 0; k < DD; k++) {
        float rk = (k < 32) ? __shfl_sync(0xffffffffu, rl0, k)
                            : __shfl_sync(0xffffffffu, rl1, k - 32);
        r20 = fmaf(rk, W_rel2[i0 * DD + k], r20);
        r21 = fmaf(rk, W_rel2[i1 * DD + k], r21);
    }
    g_R2[r * DD + i0] = r20;
    g_R2[r * DD + i1] = r21;
    float q = fmaf(p0, W_a[i0], p1 * W_a[i1]);
#pragma unroll
    for (int o = 16; o > 0; o >>= 1) q += __shfl_xor_sync(0xffffffffu, q, o);
    if (lane == 0) g_q3[r] = q + b_a[0];
}

// ---------------- 3. node tables: register-blocked 4x4 GEMM tile -------------
// Block: 128 threads = 16 tx (4 nodes each) x 8 ty (4 outputs each).
// Covers 64 nodes x 32 outputs (blockIdx.y = output half).
// Per k-step: 4 x-LDS + 4 w-LDS feed 16 FMA2 (ratio 2:1).
__global__ void __launch_bounds__(128) k_node_proj(const float* __restrict__ ent) {
    __shared__ float sX[64 * 65];   // 16.6KB, odd pad -> conflict-free
    __shared__ ull sM[32 * 65];     // 16.6KB
    __shared__ ull sVa[DD];
    int tid = threadIdx.x;
    int tx = tid & 15;              // node group
    int ty = tid >> 4;              // output group (0..7)
    int yb = blockIdx.y;
    int nbase = blockIdx.x * 64;

    // stage weights (32 rows of this half)
    for (int idx = tid; idx < 32 * DD; idx += 128) {
        int row = idx >> 6, k = idx & 63;
        sM[row * 65 + k] = g_M12[(yb * 32 + row) * DD + k];
    }
    if (yb == 0)
        for (int idx = tid; idx < DD; idx += 128) sVa[idx] = g_va[idx];
    // stage x: 2 threads per node row, 32 floats each (scalar; staging only)
    {
        int n = tid >> 1;            // 0..63
        int k0 = (tid & 1) * 32;
        int gn = nbase + n;
        if (gn >= NN) gn = NN - 1;   // clamp (writes guarded later)
        const float* xr = ent + gn * DD + k0;
        float* xw = &sX[n * 65 + k0];
#pragma unroll 8
        for (int k = 0; k < 32; k++) xw[k] = xr[k];
    }
    __syncthreads();

    // q1/q2: ty==0 threads compute for their 4 nodes
    if (yb == 0 && ty == 0) {
#pragma unroll
        for (int j = 0; j < 4; j++) {
            int n = tx * 4 + j;
            int gn = nbase + n;
            if (gn < NN) {
                const float* xrow = &sX[n * 65];
                ull q = 0ULL;
#pragma unroll 8
                for (int k = 0; k < DD; k++)
                    FMA2(q, pack2(xrow[k], xrow[k]), sVa[k], q);
                g_q1[gn] = lo2(q);
                g_q2[gn] = hi2(q);
            }
        }
    }

    ull acc[4][4];
#pragma unroll
    for (int j = 0; j < 4; j++)
#pragma unroll
        for (int ii = 0; ii < 4; ii++) acc[j][ii] = 0ULL;

#pragma unroll 4
    for (int k = 0; k < DD; k++) {
        float xv0 = sX[(tx * 4 + 0) * 65 + k];
        float xv1 = sX[(tx * 4 + 1) * 65 + k];
        float xv2 = sX[(tx * 4 + 2) * 65 + k];
        float xv3 = sX[(tx * 4 + 3) * 65 + k];
        ull w0 = sM[(ty * 4 + 0) * 65 + k];
        ull w1 = sM[(ty * 4 + 1) * 65 + k];
        ull w2 = sM[(ty * 4 + 2) * 65 + k];
        ull w3 = sM[(ty * 4 + 3) * 65 + k];
        ull x0 = pack2(xv0, xv0), x1 = pack2(xv1, xv1);
        ull x2 = pack2(xv2, xv2), x3 = pack2(xv3, xv3);
        FMA2(acc[0][0], x0, w0, acc[0][0]); FMA2(acc[0][1], x0, w1, acc[0][1]);
        FMA2(acc[0][2], x0, w2, acc[0][2]); FMA2(acc[0][3], x0, w3, acc[0][3]);
        FMA2(acc[1][0], x1, w0, acc[1][0]); FMA2(acc[1][1], x1, w1, acc[1][1]);
        FMA2(acc[1][2], x1, w2, acc[1][2]); FMA2(acc[1][3], x1, w3, acc[1][3]);
        FMA2(acc[2][0], x2, w0, acc[2][0]); FMA2(acc[2][1], x2, w1, acc[2][1]);
        FMA2(acc[2][2], x2, w2, acc[2][2]); FMA2(acc[2][3], x2, w3, acc[2][3]);
        FMA2(acc[3][0], x3, w0, acc[3][0]); FMA2(acc[3][1], x3, w1, acc[3][1]);
        FMA2(acc[3][2], x3, w2, acc[3][2]); FMA2(acc[3][3], x3, w3, acc[3][3]);
    }

    int obase = yb * 32 + ty * 4;
#pragma unroll
    for (int j = 0; j < 4; j++) {
        int gn = nbase + tx * 4 + j;
        if (gn < NN) {
            *(float4*)&g_P1[gn * DD + obase] = make_float4(
                lo2(acc[j][0]), lo2(acc[j][1]), lo2(acc[j][2]), lo2(acc[j][3]));
            *(float4*)&g_P2[gn * DD + obase] = make_float4(
                hi2(acc[j][0]), hi2(acc[j][1]), hi2(acc[j][2]), hi2(acc[j][3]));
        }
    }
}

// ---------------- 4. counts (sharded rel counters; resets lookback) ----------
__global__ void __launch_bounds__(256) k_count(const int4* __restrict__ src4,
                                               const int4* __restrict__ rel4) {
    if (blockIdx.x == 0) {
        for (int k = threadIdx.x; k < NB_N; k += 256) g_look[k] = 0ULL;
    }
    int t = blockIdx.x * blockDim.x + threadIdx.x;
    if (t >= EE / 4) return;
    int sh = threadIdx.x & (NSH - 1);
    int4 s = src4[t], r = rel4[t];
    atomicAdd(&g_src_cnt[s.x], 1);
    atomicAdd(&g_src_cnt[s.y], 1);
    atomicAdd(&g_src_cnt[s.z], 1);
    atomicAdd(&g_src_cnt[s.w], 1);
    atomicAdd(&g_rel_cnt8[(r.x * NSH + sh) * RPAD8], 1);
    atomicAdd(&g_rel_cnt8[(r.y * NSH + sh) * RPAD8], 1);
    atomicAdd(&g_rel_cnt8[(r.z * NSH + sh) * RPAD8], 1);
    atomicAdd(&g_rel_cnt8[(r.w * NSH + sh) * RPAD8], 1);
}

// ---------------- 5. fused scan (decoupled lookback; co-residency-safe) ------
__global__ void __launch_bounds__(1024) k_scan_all() {
    __shared__ int ws[32];
    __shared__ int sPrefix;
    __shared__ int sCarry;
    int b = blockIdx.x;
    int tid = threadIdx.x;
    int i = b * 1024 + tid;
    int v = (i < NN) ? g_src_cnt[i] : 0;
    int ex = blockExScan(v, ws);
    if (tid == 1023) {
        ull word = (1ULL << 32) | (ull)(unsigned)(ex + v);
        atomicExch(&g_look[b], word);
    }
    if (b == 0) {
        __syncthreads();
        if (tid == 0) sCarry = 0;
        __syncthreads();
        for (int ch = 0; ch < (RR * NSH + 1023) / 1024; ch++) {
            int idx = ch * 1024 + tid;
            int vr = (idx < RR * NSH) ? g_rel_cnt8[idx * RPAD8] : 0;
            int exr = blockExScan(vr, ws) + sCarry;
            if (idx < RR * NSH) {
                g_rel_off8[idx] = exr;
                g_rel_cur8[idx * RPAD8] = exr;
                g_rel_cnt8[idx * RPAD8] = 0;          // self-clean
            }
            __syncthreads();
            if (tid == 1023) sCarry = exr + vr;
            __syncthreads();
        }
        if (tid == 0) g_rel_off8[RR * NSH] = EE;
    }
    if (tid < 32) {
        int acc = 0;
        for (int k = tid; k < b; k += 32) {
            ull w;
            do { w = atomicAdd(&g_look[k], 0ULL); } while ((w >> 32) == 0ULL);
            acc += (int)(unsigned)w;
        }
#pragma unroll
        for (int o = 16; o > 0; o >>= 1) acc += __shfl_down_sync(0xffffffffu, acc, o);
        if (tid == 0) sPrefix = acc;
    }
    __syncthreads();
    int pre = sPrefix;
    if (i < NN) {
        int off = ex + pre;
        g_src_off[i] = off;
        g_src_cur[i] = off;
        g_src_cnt[i] = 0;                      // self-clean
    }
    if (b == 0 && tid == 0) g_src_off[NN] = EE;
}

// ---------------- 6. fill both CSRs (sharded rel cursors) --------------------
__global__ void __launch_bounds__(256) k_fill(const int4* __restrict__ src4,
                                              const int4* __restrict__ dst4,
                                              const int4* __restrict__ rel4) {
    int t = blockIdx.x * blockDim.x + threadIdx.x;
    if (t >= EE / 4) return;
    int sh = threadIdx.x & (NSH - 1);
    int4 s = src4[t], d = dst4[t], r = rel4[t];
    g_src_pay[atomicAdd(&g_src_cur[s.x], 1)] = make_int2(d.x, r.x);
    g_src_pay[atomicAdd(&g_src_cur[s.y], 1)] = make_int2(d.y, r.y);
    g_src_pay[atomicAdd(&g_src_cur[s.z], 1)] = make_int2(d.z, r.z);
    g_src_pay[atomicAdd(&g_src_cur[s.w], 1)] = make_int2(d.w, r.w);
    g_rel_pay[atomicAdd(&g_rel_cur8[(r.x * NSH + sh) * RPAD8], 1)] = make_int2(s.x, d.x);
    g_rel_pay[atomicAdd(&g_rel_cur8[(r.y * NSH + sh) * RPAD8], 1)] = make_int2(s.y, d.y);
    g_rel_pay[atomicAdd(&g_rel_cur8[(r.z * NSH + sh) * RPAD8], 1)] = make_int2(s.z, d.z);
    g_rel_pay[atomicAdd(&g_rel_cur8[(r.w * NSH + sh) * RPAD8], 1)] = make_int2(s.w, d.w);
}

// ---------------- 7. node aggregation (R8-proven) ----------------------------
__global__ void __launch_bounds__(256) k_node_agg(float* __restrict__ out) {
    const float4* P1 = (const float4*)g_P1;
    const float4* P2 = (const float4*)g_P2;
    const float4* P3 = (const float4*)g_P3p;
    int wid = threadIdx.x >> 5;
    int lane = threadIdx.x & 31;
    int n = blockIdx.x * 8 + wid;
    if (n >= NN) return;
    int j0 = g_src_off[n];
    int j1 = g_src_off[n + 1];
    int half = lane >> 4;
    int q = lane & 15;
    float q1n = g_q1[n];
    float4 acc = make_float4(0.f, 0.f, 0.f, 0.f);
    float bsum = 0.f;
    int j = j0 + half;
    for (; j + 2 < j1; j += 4) {
        int2 pA = g_src_pay[j];
        int2 pB = g_src_pay[j + 2];
        float lA = q1n + g_q2[pA.x] + g_q3[pA.y];
        float lB = q1n + g_q2[pB.x] + g_q3[pB.y];
        float bA = leaky_exp(lA), bB = leaky_exp(lB);
        float4 vA = P2[pA.x * 16 + q];
        float4 tA = P3[pA.y * 16 + q];
        float4 vB = P2[pB.x * 16 + q];
        float4 tB = P3[pB.y * 16 + q];
        acc.x = fmaf(bA, vA.x + tA.x, acc.x); acc.x = fmaf(bB, vB.x + tB.x, acc.x);
        acc.y = fmaf(bA, vA.y + tA.y, acc.y); acc.y = fmaf(bB, vB.y + tB.y, acc.y);
        acc.z = fmaf(bA, vA.z + tA.z, acc.z); acc.z = fmaf(bB, vB.z + tB.z, acc.z);
        acc.w = fmaf(bA, vA.w + tA.w, acc.w); acc.w = fmaf(bB, vB.w + tB.w, acc.w);
        bsum += bA + bB;
    }
    if (j < j1) {
        int2 p = g_src_pay[j];
        float lg = q1n + g_q2[p.x] + g_q3[p.y];
        float b = leaky_exp(lg);
        float4 v = P2[p.x * 16 + q];
        float4 tq = P3[p.y * 16 + q];
        acc.x = fmaf(b, v.x + tq.x, acc.x);
        acc.y = fmaf(b, v.y + tq.y, acc.y);
        acc.z = fmaf(b, v.z + tq.z, acc.z);
        acc.w = fmaf(b, v.w + tq.w, acc.w);
        bsum += b;
    }
    acc.x += __shfl_down_sync(0xffffffffu, acc.x, 16);
    acc.y += __shfl_down_sync(0xffffffffu, acc.y, 16);
    acc.z += __shfl_down_sync(0xffffffffu, acc.z, 16);
    acc.w += __shfl_down_sync(0xffffffffu, acc.w, 16);
    bsum  += __shfl_down_sync(0xffffffffu, bsum, 16);
    if (half == 0) {
        float4 h;
        if (j1 > j0) {
            float inv = 1.f / bsum;
            float4 p1v = P1[n * 16 + q];
            h.x = p1v.x + acc.x * inv;
            h.y = p1v.y + acc.y * inv;
            h.z = p1v.z + acc.z * inv;
            h.w = p1v.w + acc.w * inv;
        } else {
            h = make_float4(0.f, 0.f, 0.f, 0.f);
        }
        ((float4*)out)[n * 16 + q] = h;
    }
}

// ---------------- 8. fused relation pooling + output (R8-proven) -------------
__global__ void __launch_bounds__(512) k_rel_pool_out(const float4* __restrict__ h4,
                                                      const float* __restrict__ W_rel3,
                                                      const float* __restrict__ b_rel3,
                                                      float* __restrict__ out) {
    __shared__ float4 sred[16][32];
    __shared__ float smean[192];
    int r = blockIdx.x;
    int b0 = g_rel_off8[r * NSH];
    int b1 = g_rel_off8[(r + 1) * NSH];
    int cnt = b1 - b0;
    int w = threadIdx.x >> 5;
    int lane = threadIdx.x & 31;
    int isDst = lane >> 4;
    int q = lane & 15;
    float4 acc = make_float4(0.f, 0.f, 0.f, 0.f);
    int j = b0 + w;
    for (; j + 48 < b1; j += 64) {
        int2 p0 = g_rel_pay[j];
        int2 p1 = g_rel_pay[j + 16];
        int2 p2 = g_rel_pay[j + 32];
        int2 p3 = g_rel_pay[j + 48];
        int n0 = isDst ? p0.y : p0.x;
        int n1 = isDst ? p1.y : p1.x;
        int n2 = isDst ? p2.y : p2.x;
        int n3 = isDst ? p3.y : p3.x;
        float4 v0 = h4[n0 * 16 + q];
        float4 v1 = h4[n1 * 16 + q];
        float4 v2 = h4[n2 * 16 + q];
        float4 v3 = h4[n3 * 16 + q];
        acc.x += (v0.x + v1.x) + (v2.x + v3.x);
        acc.y += (v0.y + v1.y) + (v2.y + v3.y);
        acc.z += (v0.z + v1.z) + (v2.z + v3.z);
        acc.w += (v0.w + v1.w) + (v2.w + v3.w);
    }
    for (; j < b1; j += 16) {
        int2 p = g_rel_pay[j];
        int n = isDst ? p.y : p.x;
        float4 v = h4[n * 16 + q];
        acc.x += v.x; acc.y += v.y; acc.z += v.z; acc.w += v.w;
    }
    sred[w][lane] = acc;
    __syncthreads();
    if (w == 0) {
        float4 s = sred[0][lane];
#pragma unroll
        for (int k = 1; k < 16; k++) {
            float4 t = sred[k][lane];
            s.x += t.x; s.y += t.y; s.z += t.z; s.w += t.w;
        }
        float inv = 1.f / (float)max(cnt, 1);
        int base = isDst * 64 + q * 4;
        smean[base + 0] = s.x * inv;
        smean[base + 1] = s.y * inv;
        smean[base + 2] = s.z * inv;
        smean[base + 3] = s.w * inv;
    } else if (w == 1) {
        float sc = (cnt > 0) ? 1.f : 0.f;
        smean[128 + lane] = g_R2[r * DD + lane] * sc;
        smean[160 + lane] = g_R2[r * DD + 32 + lane] * sc;
    }
    __syncthreads();
    if (threadIdx.x < DD) {
        int i = threadIdx.x;
        float h = b_rel3[i];
#pragma unroll 8
        for (int jj = 0; jj < 192; jj++)
            h = fmaf(W_rel3[i * 192 + jj], smean[jj], h);
        out[NN * DD + r * DD + i] = h;
    }
}

// ---------------- launcher ---------------------------------------------------
extern "C" void kernel_launch(void* const* d_in, const int* in_sizes, int n_in,
                              void* d_out, int out_size) {
    const float* ent_embed = (const float*)d_in[0];
    const float* rel_embed = (const float*)d_in[1];
    const float* W_ent  = (const float*)d_in[2];
    const float* b_ent  = (const float*)d_in[3];
    const float* W_relL = (const float*)d_in[4];
    const float* b_relL = (const float*)d_in[5];
    const float* W_rel2 = (const float*)d_in[6];
    const float* b_rel2 = (const float*)d_in[7];
    const float* W_rel3 = (const float*)d_in[8];
    const float* b_rel3 = (const float*)d_in[9];
    const float* W_a    = (const float*)d_in[10];
    const float* b_a    = (const float*)d_in[11];
    const float* W_fc   = (const float*)d_in[12];
    const float* b_fc   = (const float*)d_in[13];
    const int* src_idx = (const int*)d_in[14];
    const int* dst_idx = (const int*)d_in[15];
    const int* rel_idx = (const int*)d_in[16];
    float* out = (float*)d_out;

    static cudaStream_t s2 = nullptr;
    static cudaEvent_t evF = nullptr, evJ = nullptr;
    if (s2 == nullptr) {
        cudaStreamCreateWithFlags(&s2, cudaStreamNonBlocking);
        cudaEventCreateWithFlags(&evF, cudaEventDisableTiming);
        cudaEventCreateWithFlags(&evJ, cudaEventDisableTiming);
    }

    const int4* s4 = (const int4*)src_idx;
    const int4* d4 = (const int4*)dst_idx;
    const int4* r4 = (const int4*)rel_idx;

    // fork (execution deps via events; submission order keeps k_node_proj in
    // the profiler's capture slot)
    cudaEventRecord(evF, 0);
    cudaStreamWaitEvent(s2, evF, 0);

    k_precompute<<<16, 256>>>(W_ent, W_relL, W_fc, b_ent, b_relL, b_fc, W_a);     // 1
    k_rel_proj<<<(RR + 3) / 4, 128>>>(rel_embed, W_relL, b_relL,
                                      W_rel2, b_rel2, W_a, b_a);                   // 2
    k_count<<<(EE / 4 + 255) / 256, 256, 0, s2>>>(s4, r4);                         // 3
    {
        dim3 grid((NN + 63) / 64, 2);
        k_node_proj<<<grid, 128>>>(ent_embed);                                     // 4
    }
    k_scan_all<<<NB_N, 1024, 0, s2>>>();                                           // 5
    k_fill<<<(EE / 4 + 255) / 256, 256, 0, s2>>>(s4, d4, r4);                      // 6
    cudaEventRecord(evJ, s2);

    // join, then aggregation + fused relation output
    cudaStreamWaitEvent(0, evJ, 0);
    k_node_agg<<<(NN + 7) / 8, 256>>>(out);                                        // 7
    k_rel_pool_out<<<RR, 512>>>((const float4*)out, W_rel3, b_rel3, out);          // 8
}

// round 17
// speedup vs baseline: 1.2298x; 1.2167x over previous
#include <cuda_runtime.h>
#include <cuda_bf16.h>
#include <math.h>

#define NN 100000
#define EE 1000000
#define RR 500
#define DD 64
#define NB_N 98            // ceil(100000/1024)
#define NSH 16             // relation-counter shards
#define RPAD8 8            // 32B stride for sharded rel counters (8000 buckets)

typedef unsigned long long ull;

#define FMA2(d, a, b, c) \
    asm("fma.rn.f32x2 %0, %1, %2, %3;" : "=l"(d) : "l"(a), "l"(b), "l"(c))

__device__ __forceinline__ ull pack2(float lo, float hi) {
    return ((ull)__float_as_uint(hi) << 32) | (ull)__float_as_uint(lo);
}
__device__ __forceinline__ float lo2(ull u) { return __uint_as_float((unsigned)u); }
__device__ __forceinline__ float hi2(ull u) { return __uint_as_float((unsigned)(u >> 32)); }

__device__ __forceinline__ unsigned f2tf32(float x) {
    unsigned r;
    asm("cvt.rna.tf32.f32 %0, %1;" : "=r"(r) : "f"(x));
    return r;
}

#define MMA_TF32(d, a0, a1, a2, a3, b0, b1) \
    asm volatile("mma.sync.aligned.m16n8k8.row.col.f32.tf32.tf32.f32 " \
        "{%0,%1,%2,%3}, {%4,%5,%6,%7}, {%8,%9}, {%0,%1,%2,%3};" \
        : "+f"((d)[0]), "+f"((d)[1]), "+f"((d)[2]), "+f"((d)[3]) \
        : "r"(a0), "r"(a1), "r"(a2), "r"(a3), "r"(b0), "r"(b1))

// ---------------- scratch (device globals; all self-cleaning) -----------------
__device__ __align__(16) float g_P1[NN * DD];
__device__ __align__(16) float g_P2[NN * DD];
__device__ float g_q1[NN];
__device__ float g_q2[NN];
__device__ __align__(16) float g_P3p[RR * DD];
__device__ float g_q3[RR];
__device__ float g_R2[RR * DD];
__device__ float g_W1[DD * DD];      // composed M1 (fp32)
__device__ float g_W2[DD * DD];      // composed M2 (fp32)
__device__ float g_M3[DD * DD];
__device__ float g_c0[DD];
__device__ ull   g_va[DD];           // packed (M1^T a, M2^T a)
__device__ int   g_src_cnt[NN];                 // zeroed by k_scan_all after read
__device__ int   g_rel_cnt8[RR * NSH * RPAD8];  // sharded; zeroed by k_scan_all
__device__ int   g_src_off[NN + 1];
__device__ int   g_rel_off8[RR * NSH + 1];      // bucket offsets (r-major, shard-minor)
__device__ int   g_src_cur[NN];
__device__ int   g_rel_cur8[RR * NSH * RPAD8];
__device__ __align__(8) int2 g_src_pay[EE];   // (dst, rel) in src-CSR order
__device__ __align__(8) int2 g_rel_pay[EE];   // (src, dst) in rel-CSR order
__device__ ull   g_look[NB_N];           // decoupled-lookback (flag<<32 | agg)

// ---------------- helpers ----------------------------------------------------
__device__ __forceinline__ int blockExScan(int v, int* warpSums) {
    int lane = threadIdx.x & 31;
    int wid  = threadIdx.x >> 5;
    int nw   = blockDim.x >> 5;
    int inc = v;
#pragma unroll
    for (int o = 1; o < 32; o <<= 1) {
        int t = __shfl_up_sync(0xffffffffu, inc, o);
        if (lane >= o) inc += t;
    }
    if (lane == 31) warpSums[wid] = inc;
    __syncthreads();
    if (wid == 0) {
        int w = (lane < nw) ? warpSums[lane] : 0;
#pragma unroll
        for (int o = 1; o < 32; o <<= 1) {
            int t = __shfl_up_sync(0xffffffffu, w, o);
            if (lane >= o) w += t;
        }
        if (lane < nw) warpSums[lane] = w;
    }
    __syncthreads();
    int base = (wid > 0) ? warpSums[wid - 1] : 0;
    return base + inc - v;   // exclusive
}

__device__ __forceinline__ float leaky_exp(float lg) {
    lg = (lg >= 0.f) ? lg : 0.01f * lg;
    return expf(lg);
}

// ---------------- 1. composed weight matrices (16 CTAs, float4-staged) -------
__global__ void __launch_bounds__(256) k_precompute(const float* __restrict__ W_ent,
                                                    const float* __restrict__ W_relL,
                                                    const float* __restrict__ W_fc,
                                                    const float* __restrict__ b_ent,
                                                    const float* __restrict__ b_relL,
                                                    const float* __restrict__ b_fc,
                                                    const float* __restrict__ W_a) {
    __shared__ float sEnt[DD * DD];
    __shared__ float sRel[DD * DD];
    __shared__ float sFc[4 * 192];
    __shared__ float sT[128];
    int tid = threadIdx.x;
    int i0 = blockIdx.x * 4;
    {
        const float4* e4 = (const float4*)W_ent;
        const float4* r4 = (const float4*)W_relL;
        float4* sE4 = (float4*)sEnt;
        float4* sR4 = (float4*)sRel;
#pragma unroll
        for (int idx = tid; idx < DD * DD / 4; idx += 256) {
            sE4[idx] = e4[idx];
            sR4[idx] = r4[idx];
        }
        const float4* f4 = (const float4*)(W_fc + i0 * 192);
        float4* sF4 = (float4*)sFc;
        if (tid < 192) sF4[tid] = f4[tid];
    }
    __syncthreads();

    int i = i0 + (tid >> 6);
    int j = tid & 63;
    int fr = (tid >> 6) * 192;
    float a1 = 0.f, a2 = 0.f, a3 = 0.f;
#pragma unroll 8
    for (int k = 0; k < DD; k++) {
        float e = sEnt[k * DD + j];
        a1 = fmaf(sFc[fr + k], e, a1);
        a2 = fmaf(sFc[fr + 64 + k], e, a2);
        a3 = fmaf(sFc[fr + 128 + k], sRel[k * DD + j], a3);
    }
    g_W1[i * DD + j] = a1;
    g_W2[i * DD + j] = a2;
    g_M3[i * DD + j] = a3;

    if (blockIdx.x == 0) {
        if (tid < DD) {
            float c = b_fc[tid];
#pragma unroll 8
            for (int k = 0; k < DD; k++) {
                c = fmaf(W_fc[tid * 192 + k], b_ent[k], c);
                c = fmaf(W_fc[tid * 192 + 64 + k], b_ent[k], c);
                c = fmaf(W_fc[tid * 192 + 128 + k], b_relL[k], c);
            }
            g_c0[tid] = c;
        }
        if (tid < 128) {
            int k = tid & 63;
            int off = (tid < 64) ? 0 : 64;
            float acc = 0.f;
#pragma unroll 8
            for (int ii = 0; ii < 64; ii++)
                acc = fmaf(W_fc[ii * 192 + off + k], W_a[ii], acc);
            sT[tid] = acc;
        }
        __syncthreads();
        if (tid < DD) {
            float v1 = 0.f, v2 = 0.f;
#pragma unroll 8
            for (int k = 0; k < DD; k++) {
                float e = sEnt[k * DD + tid];
                v1 = fmaf(e, sT[k], v1);
                v2 = fmaf(e, sT[64 + k], v2);
            }
            g_va[tid] = pack2(v1, v2);
        }
    }
}

// ---------------- 2. relation tables: P3p, q3, R2 ----------------------------
__global__ void k_rel_proj(const float* __restrict__ rel_embed,
                           const float* __restrict__ W_relL,
                           const float* __restrict__ b_relL,
                           const float* __restrict__ W_rel2,
                           const float* __restrict__ b_rel2,
                           const float* __restrict__ W_a,
                           const float* __restrict__ b_a) {
    int r = blockIdx.x * 4 + (threadIdx.x >> 5);
    int lane = threadIdx.x & 31;
    if (r >= RR) return;
    float x0 = rel_embed[r * DD + lane];
    float x1 = rel_embed[r * DD + 32 + lane];
    int i0 = lane, i1 = lane + 32;
    float rl0 = b_relL[i0], rl1 = b_relL[i1];
    float p0 = g_c0[i0], p1 = g_c0[i1];
#pragma unroll
    for (int k = 0; k < DD; k++) {
        float xk = (k < 32) ? __shfl_sync(0xffffffffu, x0, k)
                            : __shfl_sync(0xffffffffu, x1, k - 32);
        rl0 = fmaf(xk, W_relL[i0 * DD + k], rl0);
        rl1 = fmaf(xk, W_relL[i1 * DD + k], rl1);
        p0  = fmaf(xk, g_M3[i0 * DD + k], p0);
        p1  = fmaf(xk, g_M3[i1 * DD + k], p1);
    }
    g_P3p[r * DD + i0] = p0;
    g_P3p[r * DD + i1] = p1;
    float r20 = b_rel2[i0], r21 = b_rel2[i1];
#pragma unroll
    for (int k = 0; k < DD; k++) {
        float rk = (k < 32) ? __shfl_sync(0xffffffffu, rl0, k)
                            : __shfl_sync(0xffffffffu, rl1, k - 32);
        r20 = fmaf(rk, W_rel2[i0 * DD + k], r20);
        r21 = fmaf(rk, W_rel2[i1 * DD + k], r21);
    }
    g_R2[r * DD + i0] = r20;
    g_R2[r * DD + i1] = r21;
    float q = fmaf(p0, W_a[i0], p1 * W_a[i1]);
#pragma unroll
    for (int o = 16; o > 0; o >>= 1) q += __shfl_xor_sync(0xffffffffu, q, o);
    if (lane == 0) g_q3[r] = q + b_a[0];
}

// ---------------- 3a. node tables via tf32x3 tensor cores --------------------
// grid (ceil(NN/64), 2); block 128 = 4 warps x 16 nodes.
// blockIdx.y: 0 -> P1 (W1), 1 -> P2 (W2).
// D[node][out] = sum_k X[node][k] * W[out][k]
//   A (16x8, row-major) = X tile; B (8x8, col-major k x n) = W[n][k] rows.
// tf32x3: X=xh+xl, W=wh+wl; D ~= xh*wh + xh*wl + xl*wh  (error ~2^-22)
__global__ void __launch_bounds__(128) k_node_proj(const float* __restrict__ ent) {
    __shared__ unsigned sH[64 * 68];   // 17.4KB tf32-hi weights (pad 68)
    __shared__ unsigned sL[64 * 68];   // 17.4KB tf32-lo weights
    int tid = threadIdx.x;
    int mat = blockIdx.y;
    const float* W = mat ? g_W2 : g_W1;
    for (int idx = tid; idx < DD * DD; idx += 128) {
        int o = idx >> 6, k = idx & 63;
        float w = W[idx];
        unsigned h = f2tf32(w);
        sH[o * 68 + k] = h;
        sL[o * 68 + k] = f2tf32(w - __uint_as_float(h));
    }
    __syncthreads();

    int warp = tid >> 5, lane = tid & 31;
    int g = lane >> 2;        // group 0..7
    int tg = lane & 3;        // thread-in-group
    int nb = blockIdx.x * 64 + warp * 16;
    int r0 = nb + g, r1 = nb + g + 8;
    int c0 = min(r0, NN - 1), c1 = min(r1, NN - 1);

    float d[8][4];
#pragma unroll
    for (int nt = 0; nt < 8; nt++)
#pragma unroll
        for (int ii = 0; ii < 4; ii++) d[nt][ii] = 0.f;

#pragma unroll 1
    for (int kk = 0; kk < 8; kk++) {
        int k0 = kk * 8 + tg, k1 = k0 + 4;
        float x0 = ent[c0 * DD + k0];
        float x1 = ent[c1 * DD + k0];
        float x2 = ent[c0 * DD + k1];
        float x3 = ent[c1 * DD + k1];
        unsigned ah0 = f2tf32(x0), ah1 = f2tf32(x1);
        unsigned ah2 = f2tf32(x2), ah3 = f2tf32(x3);
        unsigned al0 = f2tf32(x0 - __uint_as_float(ah0));
        unsigned al1 = f2tf32(x1 - __uint_as_float(ah1));
        unsigned al2 = f2tf32(x2 - __uint_as_float(ah2));
        unsigned al3 = f2tf32(x3 - __uint_as_float(ah3));
#pragma unroll
        for (int nt = 0; nt < 8; nt++) {
            int ob = (nt * 8 + g) * 68;
            unsigned bh0 = sH[ob + k0], bh1 = sH[ob + k1];
            unsigned bl0 = sL[ob + k0], bl1 = sL[ob + k1];
            MMA_TF32(d[nt], ah0, ah1, ah2, ah3, bh0, bh1);
            MMA_TF32(d[nt], ah0, ah1, ah2, ah3, bl0, bl1);
            MMA_TF32(d[nt], al0, al1, al2, al3, bh0, bh1);
        }
    }

    float* P = mat ? g_P2 : g_P1;
#pragma unroll
    for (int nt = 0; nt < 8; nt++) {
        int col = nt * 8 + 2 * tg;
        if (r0 < NN) *(float2*)&P[r0 * DD + col] = make_float2(d[nt][0], d[nt][1]);
        if (r1 < NN) *(float2*)&P[r1 * DD + col] = make_float2(d[nt][2], d[nt][3]);
    }
}

// ---------------- 3b. q1/q2 from va ------------------------------------------
__global__ void __launch_bounds__(128) k_qcalc(const float* __restrict__ ent) {
    __shared__ ull sVa[DD];
    for (int idx = threadIdx.x; idx < DD; idx += 128) sVa[idx] = g_va[idx];
    __syncthreads();
    int node = blockIdx.x * 128 + threadIdx.x;
    if (node >= NN) return;
    const float4* xr = (const float4*)(ent + node * DD);
    ull qa = 0ULL, qb = 0ULL;
#pragma unroll 4
    for (int u = 0; u < 16; u++) {
        float4 v = xr[u];
        FMA2(qa, pack2(v.x, v.x), sVa[4 * u + 0], qa);
        FMA2(qb, pack2(v.y, v.y), sVa[4 * u + 1], qb);
        FMA2(qa, pack2(v.z, v.z), sVa[4 * u + 2], qa);
        FMA2(qb, pack2(v.w, v.w), sVa[4 * u + 3], qb);
    }
    g_q1[node] = lo2(qa) + lo2(qb);
    g_q2[node] = hi2(qa) + hi2(qb);
}

// ---------------- 4. counts (sharded rel counters; resets lookback) ----------
__global__ void __launch_bounds__(256) k_count(const int4* __restrict__ src4,
                                               const int4* __restrict__ rel4) {
    if (blockIdx.x == 0) {
        for (int k = threadIdx.x; k < NB_N; k += 256) g_look[k] = 0ULL;
    }
    int t = blockIdx.x * blockDim.x + threadIdx.x;
    if (t >= EE / 4) return;
    int sh = threadIdx.x & (NSH - 1);
    int4 s = src4[t], r = rel4[t];
    atomicAdd(&g_src_cnt[s.x], 1);
    atomicAdd(&g_src_cnt[s.y], 1);
    atomicAdd(&g_src_cnt[s.z], 1);
    atomicAdd(&g_src_cnt[s.w], 1);
    atomicAdd(&g_rel_cnt8[(r.x * NSH + sh) * RPAD8], 1);
    atomicAdd(&g_rel_cnt8[(r.y * NSH + sh) * RPAD8], 1);
    atomicAdd(&g_rel_cnt8[(r.z * NSH + sh) * RPAD8], 1);
    atomicAdd(&g_rel_cnt8[(r.w * NSH + sh) * RPAD8], 1);
}

// ---------------- 5. fused scan (decoupled lookback; co-residency-safe) ------
__global__ void __launch_bounds__(1024) k_scan_all() {
    __shared__ int ws[32];
    __shared__ int sPrefix;
    __shared__ int sCarry;
    int b = blockIdx.x;
    int tid = threadIdx.x;
    int i = b * 1024 + tid;
    int v = (i < NN) ? g_src_cnt[i] : 0;
    int ex = blockExScan(v, ws);
    if (tid == 1023) {
        ull word = (1ULL << 32) | (ull)(unsigned)(ex + v);
        atomicExch(&g_look[b], word);
    }
    if (b == 0) {
        __syncthreads();
        if (tid == 0) sCarry = 0;
        __syncthreads();
        for (int ch = 0; ch < (RR * NSH + 1023) / 1024; ch++) {
            int idx = ch * 1024 + tid;
            int vr = (idx < RR * NSH) ? g_rel_cnt8[idx * RPAD8] : 0;
            int exr = blockExScan(vr, ws) + sCarry;
            if (idx < RR * NSH) {
                g_rel_off8[idx] = exr;
                g_rel_cur8[idx * RPAD8] = exr;
                g_rel_cnt8[idx * RPAD8] = 0;          // self-clean
            }
            __syncthreads();
            if (tid == 1023) sCarry = exr + vr;
            __syncthreads();
        }
        if (tid == 0) g_rel_off8[RR * NSH] = EE;
    }
    if (tid < 32) {
        int acc = 0;
        for (int k = tid; k < b; k += 32) {
            ull w;
            do { w = atomicAdd(&g_look[k], 0ULL); } while ((w >> 32) == 0ULL);
            acc += (int)(unsigned)w;
        }
#pragma unroll
        for (int o = 16; o > 0; o >>= 1) acc += __shfl_down_sync(0xffffffffu, acc, o);
        if (tid == 0) sPrefix = acc;
    }
    __syncthreads();
    int pre = sPrefix;
    if (i < NN) {
        int off = ex + pre;
        g_src_off[i] = off;
        g_src_cur[i] = off;
        g_src_cnt[i] = 0;                      // self-clean
    }
    if (b == 0 && tid == 0) g_src_off[NN] = EE;
}

// ---------------- 6. fill both CSRs (sharded rel cursors) --------------------
__global__ void __launch_bounds__(256) k_fill(const int4* __restrict__ src4,
                                              const int4* __restrict__ dst4,
                                              const int4* __restrict__ rel4) {
    int t = blockIdx.x * blockDim.x + threadIdx.x;
    if (t >= EE / 4) return;
    int sh = threadIdx.x & (NSH - 1);
    int4 s = src4[t], d = dst4[t], r = rel4[t];
    g_src_pay[atomicAdd(&g_src_cur[s.x], 1)] = make_int2(d.x, r.x);
    g_src_pay[atomicAdd(&g_src_cur[s.y], 1)] = make_int2(d.y, r.y);
    g_src_pay[atomicAdd(&g_src_cur[s.z], 1)] = make_int2(d.z, r.z);
    g_src_pay[atomicAdd(&g_src_cur[s.w], 1)] = make_int2(d.w, r.w);
    g_rel_pay[atomicAdd(&g_rel_cur8[(r.x * NSH + sh) * RPAD8], 1)] = make_int2(s.x, d.x);
    g_rel_pay[atomicAdd(&g_rel_cur8[(r.y * NSH + sh) * RPAD8], 1)] = make_int2(s.y, d.y);
    g_rel_pay[atomicAdd(&g_rel_cur8[(r.z * NSH + sh) * RPAD8], 1)] = make_int2(s.z, d.z);
    g_rel_pay[atomicAdd(&g_rel_cur8[(r.w * NSH + sh) * RPAD8], 1)] = make_int2(s.w, d.w);
}

// ---------------- 7. node aggregation (R8-proven) ----------------------------
__global__ void __launch_bounds__(256) k_node_agg(float* __restrict__ out) {
    const float4* P1 = (const float4*)g_P1;
    const float4* P2 = (const float4*)g_P2;
    const float4* P3 = (const float4*)g_P3p;
    int wid = threadIdx.x >> 5;
    int lane = threadIdx.x & 31;
    int n = blockIdx.x * 8 + wid;
    if (n >= NN) return;
    int j0 = g_src_off[n];
    int j1 = g_src_off[n + 1];
    int half = lane >> 4;
    int q = lane & 15;
    float q1n = g_q1[n];
    float4 acc = make_float4(0.f, 0.f, 0.f, 0.f);
    float bsum = 0.f;
    int j = j0 + half;
    for (; j + 2 < j1; j += 4) {
        int2 pA = g_src_pay[j];
        int2 pB = g_src_pay[j + 2];
        float lA = q1n + g_q2[pA.x] + g_q3[pA.y];
        float lB = q1n + g_q2[pB.x] + g_q3[pB.y];
        float bA = leaky_exp(lA), bB = leaky_exp(lB);
        float4 vA = P2[pA.x * 16 + q];
        float4 tA = P3[pA.y * 16 + q];
        float4 vB = P2[pB.x * 16 + q];
        float4 tB = P3[pB.y * 16 + q];
        acc.x = fmaf(bA, vA.x + tA.x, acc.x); acc.x = fmaf(bB, vB.x + tB.x, acc.x);
        acc.y = fmaf(bA, vA.y + tA.y, acc.y); acc.y = fmaf(bB, vB.y + tB.y, acc.y);
        acc.z = fmaf(bA, vA.z + tA.z, acc.z); acc.z = fmaf(bB, vB.z + tB.z, acc.z);
        acc.w = fmaf(bA, vA.w + tA.w, acc.w); acc.w = fmaf(bB, vB.w + tB.w, acc.w);
        bsum += bA + bB;
    }
    if (j < j1) {
        int2 p = g_src_pay[j];
        float lg = q1n + g_q2[p.x] + g_q3[p.y];
        float b = leaky_exp(lg);
        float4 v = P2[p.x * 16 + q];
        float4 tq = P3[p.y * 16 + q];
        acc.x = fmaf(b, v.x + tq.x, acc.x);
        acc.y = fmaf(b, v.y + tq.y, acc.y);
        acc.z = fmaf(b, v.z + tq.z, acc.z);
        acc.w = fmaf(b, v.w + tq.w, acc.w);
        bsum += b;
    }
    acc.x += __shfl_down_sync(0xffffffffu, acc.x, 16);
    acc.y += __shfl_down_sync(0xffffffffu, acc.y, 16);
    acc.z += __shfl_down_sync(0xffffffffu, acc.z, 16);
    acc.w += __shfl_down_sync(0xffffffffu, acc.w, 16);
    bsum  += __shfl_down_sync(0xffffffffu, bsum, 16);
    if (half == 0) {
        float4 h;
        if (j1 > j0) {
            float inv = 1.f / bsum;
            float4 p1v = P1[n * 16 + q];
            h.x = p1v.x + acc.x * inv;
            h.y = p1v.y + acc.y * inv;
            h.z = p1v.z + acc.z * inv;
            h.w = p1v.w + acc.w * inv;
        } else {
            h = make_float4(0.f, 0.f, 0.f, 0.f);
        }
        ((float4*)out)[n * 16 + q] = h;
    }
}

// ---------------- 8. fused relation pooling + output (R8-proven) -------------
__global__ void __launch_bounds__(512) k_rel_pool_out(const float4* __restrict__ h4,
                                                      const float* __restrict__ W_rel3,
                                                      const float* __restrict__ b_rel3,
                                                      float* __restrict__ out) {
    __shared__ float4 sred[16][32];
    __shared__ float smean[192];
    int r = blockIdx.x;
    int b0 = g_rel_off8[r * NSH];
    int b1 = g_rel_off8[(r + 1) * NSH];
    int cnt = b1 - b0;
    int w = threadIdx.x >> 5;
    int lane = threadIdx.x & 31;
    int isDst = lane >> 4;
    int q = lane & 15;
    float4 acc = make_float4(0.f, 0.f, 0.f, 0.f);
    int j = b0 + w;
    for (; j + 48 < b1; j += 64) {
        int2 p0 = g_rel_pay[j];
        int2 p1 = g_rel_pay[j + 16];
        int2 p2 = g_rel_pay[j + 32];
        int2 p3 = g_rel_pay[j + 48];
        int n0 = isDst ? p0.y : p0.x;
        int n1 = isDst ? p1.y : p1.x;
        int n2 = isDst ? p2.y : p2.x;
        int n3 = isDst ? p3.y : p3.x;
        float4 v0 = h4[n0 * 16 + q];
        float4 v1 = h4[n1 * 16 + q];
        float4 v2 = h4[n2 * 16 + q];
        float4 v3 = h4[n3 * 16 + q];
        acc.x += (v0.x + v1.x) + (v2.x + v3.x);
        acc.y += (v0.y + v1.y) + (v2.y + v3.y);
        acc.z += (v0.z + v1.z) + (v2.z + v3.z);
        acc.w += (v0.w + v1.w) + (v2.w + v3.w);
    }
    for (; j < b1; j += 16) {
        int2 p = g_rel_pay[j];
        int n = isDst ? p.y : p.x;
        float4 v = h4[n * 16 + q];
        acc.x += v.x; acc.y += v.y; acc.z += v.z; acc.w += v.w;
    }
    sred[w][lane] = acc;
    __syncthreads();
    if (w == 0) {
        float4 s = sred[0][lane];
#pragma unroll
        for (int k = 1; k < 16; k++) {
            float4 t = sred[k][lane];
            s.x += t.x; s.y += t.y; s.z += t.z; s.w += t.w;
        }
        float inv = 1.f / (float)max(cnt, 1);
        int base = isDst * 64 + q * 4;
        smean[base + 0] = s.x * inv;
        smean[base + 1] = s.y * inv;
        smean[base + 2] = s.z * inv;
        smean[base + 3] = s.w * inv;
    } else if (w == 1) {
        float sc = (cnt > 0) ? 1.f : 0.f;
        smean[128 + lane] = g_R2[r * DD + lane] * sc;
        smean[160 + lane] = g_R2[r * DD + 32 + lane] * sc;
    }
    __syncthreads();
    if (threadIdx.x < DD) {
        int i = threadIdx.x;
        float h = b_rel3[i];
#pragma unroll 8
        for (int jj = 0; jj < 192; jj++)
            h = fmaf(W_rel3[i * 192 + jj], smean[jj], h);
        out[NN * DD + r * DD + i] = h;
    }
}

// ---------------- launcher ---------------------------------------------------
extern "C" void kernel_launch(void* const* d_in, const int* in_sizes, int n_in,
                              void* d_out, int out_size) {
    const float* ent_embed = (const float*)d_in[0];
    const float* rel_embed = (const float*)d_in[1];
    const float* W_ent  = (const float*)d_in[2];
    const float* b_ent  = (const float*)d_in[3];
    const float* W_relL = (const float*)d_in[4];
    const float* b_relL = (const float*)d_in[5];
    const float* W_rel2 = (const float*)d_in[6];
    const float* b_rel2 = (const float*)d_in[7];
    const float* W_rel3 = (const float*)d_in[8];
    const float* b_rel3 = (const float*)d_in[9];
    const float* W_a    = (const float*)d_in[10];
    const float* b_a    = (const float*)d_in[11];
    const float* W_fc   = (const float*)d_in[12];
    const float* b_fc   = (const float*)d_in[13];
    const int* src_idx = (const int*)d_in[14];
    const int* dst_idx = (const int*)d_in[15];
    const int* rel_idx = (const int*)d_in[16];
    float* out = (float*)d_out;

    static cudaStream_t s2 = nullptr;
    static cudaEvent_t evF = nullptr, evJ = nullptr;
    if (s2 == nullptr) {
        cudaStreamCreateWithFlags(&s2, cudaStreamNonBlocking);
        cudaEventCreateWithFlags(&evF, cudaEventDisableTiming);
        cudaEventCreateWithFlags(&evJ, cudaEventDisableTiming);
    }

    const int4* s4 = (const int4*)src_idx;
    const int4* d4 = (const int4*)dst_idx;
    const int4* r4 = (const int4*)rel_idx;

    // fork (execution deps via events; submission order keeps k_node_proj in
    // the profiler's capture slot)
    cudaEventRecord(evF, 0);
    cudaStreamWaitEvent(s2, evF, 0);

    k_precompute<<<16, 256>>>(W_ent, W_relL, W_fc, b_ent, b_relL, b_fc, W_a);     // 1
    k_rel_proj<<<(RR + 3) / 4, 128>>>(rel_embed, W_relL, b_relL,
                                      W_rel2, b_rel2, W_a, b_a);                   // 2
    k_count<<<(EE / 4 + 255) / 256, 256, 0, s2>>>(s4, r4);                         // 3
    {
        dim3 grid((NN + 63) / 64, 2);
        k_node_proj<<<grid, 128>>>(ent_embed);                                     // 4
    }
    k_qcalc<<<(NN + 127) / 128, 128>>>(ent_embed);                                 // 5
    k_scan_all<<<NB_N, 1024, 0, s2>>>();                                           // 6
    k_fill<<<(EE / 4 + 255) / 256, 256, 0, s2>>>(s4, d4, r4);                      // 7
    cudaEventRecord(evJ, s2);

    // join, then aggregation + fused relation output
    cudaStreamWaitEvent(0, evJ, 0);
    k_node_agg<<<(NN + 7) / 8, 256>>>(out);                                        // 8
    k_rel_pool_out<<<RR, 512>>>((const float4*)out, W_rel3, b_rel3, out);          // 9
}